// round 12
// baseline (speedup 1.0000x reference)
#include <cuda_runtime.h>
#include <cuda_fp16.h>
#include <cstdint>

#define BN 8
#define IC 512
#define OC 512
#define HH 32
#define WW 32

#define RC_DENSE 0.04419417382415922f     // 1/sqrt(512)
#define RC_CONV  0.014731391274719739f    // 1/sqrt(9*512)

// ---------------- device scratch (no runtime allocation) ----------------
__device__ float g_style[BN * IC];
__device__ float g_scale[BN * OC];
__device__ float g_ss[IC * OC];
// weights transposed to [tap][oc][ic], fp16
__device__ __align__(128) __half g_wq[9 * OC * IC];
// modulated input in NHWC: [b][h][w][ic], fp16
__device__ __align__(128) __half g_xm[BN * HH * WW * IC];

// ---------------- prologue kernels ----------------
__global__ void style_kernel(const float* __restrict__ w,
                             const float* __restrict__ dense_w,
                             const float* __restrict__ dense_b) {
    __shared__ float wrow[IC];
    int b = blockIdx.x;
    for (int j = threadIdx.x; j < IC; j += blockDim.x) wrow[j] = w[b * IC + j];
    __syncthreads();
    for (int i = threadIdx.x; i < IC; i += blockDim.x) {
        float acc = 0.f;
        #pragma unroll 8
        for (int j = 0; j < IC; j++) acc = fmaf(wrow[j], dense_w[j * IC + i], acc);
        g_style[b * IC + i] = RC_DENSE * acc + dense_b[i] + 1.0f;
    }
}

// conv_w[k][ic][oc] -> wq[k][oc][ic] (fp16) AND ss[ic][oc] = sum_k w^2 (fused)
__global__ void wtrans_kernel(const float* __restrict__ conv_w) {
    __shared__ float tile[32][33];
    int ic0 = blockIdx.x * 32, oc0 = blockIdx.y * 32;
    int t = threadIdx.x, col = t & 31, row0 = t >> 5;
    int r = t >> 3, pp = t & 7;
    float ssacc[4] = {0.f, 0.f, 0.f, 0.f};
    for (int k = 0; k < 9; k++) {
        __syncthreads();
        #pragma unroll
        for (int rr = 0; rr < 4; rr++) {
            int i = rr * 8 + row0;  // ic
            float v = conv_w[((size_t)(k * IC + ic0 + i)) * OC + oc0 + col];
            tile[i][col] = v;
            ssacc[rr] = fmaf(v, v, ssacc[rr]);
        }
        __syncthreads();
        size_t base = ((size_t)(k * OC + oc0 + r)) * IC + ic0;
        #pragma unroll
        for (int it = 0; it < 2; it++) {
            int ci = 2 * (it * 8 + pp);
            *(__half2*)(g_wq + base + ci) =
                __halves2half2(__float2half_rn(tile[ci][r]), __float2half_rn(tile[ci + 1][r]));
        }
    }
    #pragma unroll
    for (int rr = 0; rr < 4; rr++)
        g_ss[(size_t)(ic0 + rr * 8 + row0) * OC + oc0 + col] = ssacc[rr];
}

__global__ void demod_kernel() {
    __shared__ float s2[IC];
    int b = blockIdx.x;
    for (int i = threadIdx.x; i < IC; i += blockDim.x) {
        float s = g_style[b * IC + i];
        s2[i] = s * s;
    }
    __syncthreads();
    for (int oc = threadIdx.x; oc < OC; oc += blockDim.x) {
        float acc = 0.f;
        #pragma unroll 8
        for (int i = 0; i < IC; i++) acc = fmaf(s2[i], g_ss[i * OC + oc], acc);
        g_scale[b * OC + oc] = RC_CONV * rsqrtf(RC_CONV * RC_CONV * acc + 1e-8f);
    }
}

// x[b][ic][h][w] * style[b][ic] -> xm[b][h][w][ic] (fp16)
__global__ void xtrans_kernel(const float* __restrict__ x) {
    __shared__ float tile[32][33];
    int ic0 = blockIdx.x * 32, h = blockIdx.y, b = blockIdx.z;
    int t = threadIdx.x, col = t & 31, row0 = t >> 5;
    #pragma unroll
    for (int rr = 0; rr < 4; rr++) {
        int i = rr * 8 + row0;  // ic
        tile[i][col] = x[(((size_t)b * IC + ic0 + i) * HH + h) * WW + col] * g_style[b * IC + ic0 + i];
    }
    __syncthreads();
    int w = t >> 3, pp = t & 7;
    size_t base = (((size_t)b * HH + h) * WW + w) * IC + ic0;
    #pragma unroll
    for (int it = 0; it < 2; it++) {
        int ci = 2 * (it * 8 + pp);
        *(__half2*)(g_xm + base + ci) =
            __halves2half2(__float2half_rn(tile[ci][w]), __float2half_rn(tile[ci + 1][w]));
    }
}

// ---------------- main mma.sync conv kernel ----------------
// CTA tile: M=64 (2 h x 32 w) x N=64 oc. 128 threads = 4 warps (2M x 2N),
// warp tile 32x32. Grid 16x8x8 = 1024 CTAs (~6.92/SM) for load balance.
// A staged per ic-chunk as 4x34 halo; B(tap) fp16, 3-stage cp.async pipeline.
#define KC 32
#define PAD_A 40
#define PAD_B 40

// smem offsets in halves
#define A_O 0
#define B_O(buf) (5440 + (buf) * 2560)
#define SM_HALVES 13120      // 26240 bytes

__device__ __forceinline__ void mma_f16(float* c,
                                        const uint32_t* a, uint32_t b0, uint32_t b1) {
    asm volatile(
        "mma.sync.aligned.m16n8k16.row.col.f32.f16.f16.f32 "
        "{%0,%1,%2,%3}, {%4,%5,%6,%7}, {%8,%9}, {%0,%1,%2,%3};"
        : "+f"(c[0]), "+f"(c[1]), "+f"(c[2]), "+f"(c[3])
        : "r"(a[0]), "r"(a[1]), "r"(a[2]), "r"(a[3]), "r"(b0), "r"(b1));
}

__device__ __forceinline__ void ldsm4(uint32_t* r, uint32_t a) {
    asm volatile("ldmatrix.sync.aligned.m8n8.x4.shared.b16 {%0,%1,%2,%3}, [%4];"
                 : "=r"(r[0]), "=r"(r[1]), "=r"(r[2]), "=r"(r[3]) : "r"(a));
}

__device__ __forceinline__ void cp16(uint32_t dst, const void* src, bool v) {
    asm volatile("cp.async.ca.shared.global [%0], [%1], 16, %2;"
                 :: "r"(dst), "l"(src), "r"(v ? 16 : 0) : "memory");
}
#define CP_COMMIT() asm volatile("cp.async.commit_group;" ::: "memory")
#define CP_WAIT0()  asm volatile("cp.async.wait_group 0;" ::: "memory")
#define CP_WAIT1()  asm volatile("cp.async.wait_group 1;" ::: "memory")

__device__ __forceinline__ uint32_t smem_u32(const void* p) {
    uint32_t a;
    asm("{ .reg .u64 t; cvta.to.shared.u64 t, %1; cvt.u32.u64 %0, t; }" : "=r"(a) : "l"(p));
    return a;
}

__global__ __launch_bounds__(128, 6)
void conv_mma_kernel(float* __restrict__ y) {
    extern __shared__ unsigned short sm[];
    const uint32_t smb = smem_u32(sm);

    const int tid = threadIdx.x;
    const int wid = tid >> 5, lane = tid & 31;
    const int gr = lane >> 2, tig = lane & 3;
    const int wm = wid & 1;        // warp h-row (0/1)
    const int wn = wid >> 1;       // warp oc half (0/1)

    const int h0 = blockIdx.x * 2;
    const int oc0 = blockIdx.y * 64;
    const int b = blockIdx.z;

    // ---- ldmatrix lane address components ----
    const int r16 = ((lane >> 3) & 1) * 8 + (lane & 7);
    const int kq8 = (lane >> 4) * 8;
    // A: halo row (wm+1+dh), col (w+1+dw); w = mt*16 + r16
    const int aoff0 = ((wm + 1) * 34 + r16 + 1) * PAD_A + kq8;
    const int rb = (lane & 7) + ((lane >> 4) & 1) * 8;
    const int kb8 = ((lane >> 3) & 1) * 8;
    const int boff = (wn * 32 + rb) * PAD_B + kb8;

    // ---- B loader coords: 2 threads per row, 32B each (KC=32) ----
    const int rB = tid >> 1, halfB = tid & 1;
    const size_t bRowBase = (size_t)(oc0 + rB) * IC + halfB * 16;
    const uint32_t bdst = (uint32_t)(rB * PAD_B + halfB * 16) * 2;

    float acc[2][4][4];
    #pragma unroll
    for (int mt = 0; mt < 2; mt++)
        #pragma unroll
        for (int nt = 0; nt < 4; nt++)
            #pragma unroll
            for (int q = 0; q < 4; q++) acc[mt][nt][q] = 0.f;

    for (int cc = 0; cc < 16; cc++) {
        const int ic0 = cc * KC;
        __syncthreads();   // protect A halo + B buffers from previous chunk's readers

        // group 0: A halo (136 positions x 64B) + B tap0 -> buf0
        for (int e = tid; e < 544; e += 128) {
            int pos = e >> 2, j = e & 3;
            int hi_ = pos / 34, wi_ = pos % 34;
            int ha = h0 + hi_ - 1, wa = wi_ - 1;
            bool va = ((unsigned)ha < HH) && ((unsigned)wa < WW);
            size_t aidx = (((size_t)b * HH + (va ? ha : 0)) * WW + (va ? wa : 0)) * IC;
            cp16(smb + (uint32_t)(pos * PAD_A + j * 8) * 2, g_xm + aidx + ic0 + j * 8, va);
        }
        {
            const size_t src = bRowBase + ic0;
            uint32_t d_ = smb + (uint32_t)B_O(0) * 2 + bdst;
            cp16(d_,      g_wq + src, true);
            cp16(d_ + 16, g_wq + src + 8, true);
        }
        CP_COMMIT();
        // group 1: B tap1 -> buf1
        {
            const size_t src = (size_t)OC * IC + bRowBase + ic0;
            uint32_t d_ = smb + (uint32_t)B_O(1) * 2 + bdst;
            cp16(d_,      g_wq + src, true);
            cp16(d_ + 16, g_wq + src + 8, true);
        }
        CP_COMMIT();

        #pragma unroll
        for (int kk = 0; kk < 9; kk++) {
            if (kk < 7) { CP_WAIT1(); } else { CP_WAIT0(); }
            __syncthreads();
            if (kk < 7) {   // prefetch tap kk+2 -> buf (kk+2)%3
                const size_t src = (size_t)(kk + 2) * OC * IC + bRowBase + ic0;
                uint32_t d_ = smb + (uint32_t)B_O((kk + 2) % 3) * 2 + bdst;
                cp16(d_,      g_wq + src, true);
                cp16(d_ + 16, g_wq + src + 8, true);
                CP_COMMIT();
            }

            // ---- compute tap kk from buf kk%3 ----
            const int dh = kk / 3 - 1, dw = kk % 3 - 1;
            const int tsh = (dh * 34 + dw) * PAD_A;
            const uint32_t bbase = smb + (uint32_t)(B_O(kk % 3) + boff) * 2;

            #pragma unroll
            for (int ks = 0; ks < 2; ks++) {
                uint32_t ah[2][4];
                #pragma unroll
                for (int mt = 0; mt < 2; mt++) {
                    uint32_t aa = smb + (uint32_t)(aoff0 + mt * 16 * PAD_A + tsh + ks * 16) * 2;
                    ldsm4(ah[mt], aa);
                }
                #pragma unroll
                for (int np = 0; np < 2; np++) {
                    uint32_t bh[4];
                    uint32_t ba = bbase + (uint32_t)(np * 16 * PAD_B + ks * 16) * 2;
                    ldsm4(bh, ba);
                    // same-accumulator distance = 4
                    mma_f16(acc[0][2 * np],     ah[0], bh[0], bh[1]);
                    mma_f16(acc[1][2 * np],     ah[1], bh[0], bh[1]);
                    mma_f16(acc[0][2 * np + 1], ah[0], bh[2], bh[3]);
                    mma_f16(acc[1][2 * np + 1], ah[1], bh[2], bh[3]);
                }
            }
        }
    }

    // ---- epilogue: demodulate + store ----
    // warp wm covers h-row h0+wm; thread element (mt,nt,q):
    //   w = mt*16 + gr (+8 for q>=2), oc = oc0 + wn*32 + nt*8 + tig*2 + (q&1)
    const int h = h0 + wm;
    float scl[4][2];
    #pragma unroll
    for (int nt = 0; nt < 4; nt++) {
        int oc = oc0 + wn * 32 + nt * 8 + tig * 2;
        scl[nt][0] = g_scale[b * OC + oc];
        scl[nt][1] = g_scale[b * OC + oc + 1];
    }
    #pragma unroll
    for (int mt = 0; mt < 2; mt++) {
        int w0 = mt * 16 + gr;
        #pragma unroll
        for (int nt = 0; nt < 4; nt++) {
            int oc = oc0 + wn * 32 + nt * 8 + tig * 2;
            size_t base0 = (((size_t)b * OC + oc) * HH + h) * WW;
            size_t base1 = base0 + (size_t)HH * WW;
            y[base0 + w0]     = acc[mt][nt][0] * scl[nt][0];
            y[base1 + w0]     = acc[mt][nt][1] * scl[nt][1];
            y[base0 + w0 + 8] = acc[mt][nt][2] * scl[nt][0];
            y[base1 + w0 + 8] = acc[mt][nt][3] * scl[nt][1];
        }
    }
}

// ---------------------------------------------------------------------------
extern "C" void kernel_launch(void* const* d_in, const int* in_sizes, int n_in,
                              void* d_out, int out_size) {
    const float* x       = (const float*)d_in[0];
    const float* w       = (const float*)d_in[1];
    const float* conv_w  = (const float*)d_in[2];
    const float* dense_w = (const float*)d_in[3];
    const float* dense_b = (const float*)d_in[4];
    float* y = (float*)d_out;

    style_kernel<<<BN, 256>>>(w, dense_w, dense_b);
    wtrans_kernel<<<dim3(IC / 32, OC / 32), 256>>>(conv_w);   // + fused ss
    demod_kernel<<<BN, 512>>>();
    xtrans_kernel<<<dim3(IC / 32, HH, BN), 256>>>(x);

    static bool attr_set = false;
    if (!attr_set) {
        cudaFuncSetAttribute(conv_mma_kernel,
                             cudaFuncAttributeMaxDynamicSharedMemorySize, SM_HALVES * 2);
        attr_set = true;
    }
    conv_mma_kernel<<<dim3(16, 8, 8), 128, SM_HALVES * 2>>>(y);
}